// round 1
// baseline (speedup 1.0000x reference)
#include <cuda_runtime.h>
#include <math_constants.h>

// CrossEntropy: B=16384 rows, C=4096 cols.
// loss[b] = log(sum_c exp(p[b,c])) - sum_{c: t==1} p[b,c],  p = softmax(x, axis=1)
// output  = mean_b loss[b]   (single fp32 scalar)

#define B_ROWS 16384
#define C_COLS 4096
#define TPB    256          // threads per block (one block per row)
#define NWARPS (TPB / 32)
#define VPT    4            // float4 loads per thread -> 16 elements/thread

__device__ float g_losses[B_ROWS];   // per-row loss scratch (device global, no alloc)

__device__ __forceinline__ float warp_reduce_sum(float v) {
#pragma unroll
    for (int o = 16; o > 0; o >>= 1) v += __shfl_xor_sync(0xFFFFFFFFu, v, o);
    return v;
}
__device__ __forceinline__ float warp_reduce_max(float v) {
#pragma unroll
    for (int o = 16; o > 0; o >>= 1) v = fmaxf(v, __shfl_xor_sync(0xFFFFFFFFu, v, o));
    return v;
}

// Block reduce: warp shuffle + shared broadcast. Everyone returns the result.
__device__ __forceinline__ float block_reduce_sum(float v, float* sh, int tid) {
    v = warp_reduce_sum(v);
    if ((tid & 31) == 0) sh[tid >> 5] = v;
    __syncthreads();
    float r = 0.0f;
#pragma unroll
    for (int i = 0; i < NWARPS; i++) r += sh[i];
    __syncthreads();
    return r;
}
__device__ __forceinline__ float block_reduce_max(float v, float* sh, int tid) {
    v = warp_reduce_max(v);
    if ((tid & 31) == 0) sh[tid >> 5] = v;
    __syncthreads();
    float r = -CUDART_INF_F;
#pragma unroll
    for (int i = 0; i < NWARPS; i++) r = fmaxf(r, sh[i]);
    __syncthreads();
    return r;
}

__global__ __launch_bounds__(TPB, 8)
void ce_row_kernel(const float* __restrict__ x, const int* __restrict__ t) {
    const int row = blockIdx.x;
    const int tid = threadIdx.x;

    const float4* x4 = reinterpret_cast<const float4*>(x + (size_t)row * C_COLS);
    const int4*   t4 = reinterpret_cast<const int4*>(t + (size_t)row * C_COLS);

    __shared__ float sh[NWARPS];

    // ---- Phase 1: load row into registers, find max -------------------------
    float4 v[VPT];
    float lmax = -CUDART_INF_F;
#pragma unroll
    for (int i = 0; i < VPT; i++) {
        v[i] = x4[tid + i * TPB];
        lmax = fmaxf(lmax, fmaxf(fmaxf(v[i].x, v[i].y), fmaxf(v[i].z, v[i].w)));
    }
    const float m = block_reduce_max(lmax, sh, tid);

    // ---- Phase 2: exp(x - m) in registers, sum for softmax denominator ------
    float lsum = 0.0f;
#pragma unroll
    for (int i = 0; i < VPT; i++) {
        v[i].x = __expf(v[i].x - m);
        v[i].y = __expf(v[i].y - m);
        v[i].z = __expf(v[i].z - m);
        v[i].w = __expf(v[i].w - m);
        lsum += (v[i].x + v[i].y) + (v[i].z + v[i].w);
    }
    const float denom = block_reduce_sum(lsum, sh, tid);
    const float rinv  = __fdividef(1.0f, denom);

    // ---- Phase 3: p = e * rinv; accumulate exp(p) and p*mask ----------------
    float a = 0.0f;  // sum exp(p)
    float b = 0.0f;  // sum p * (t == 1)
#pragma unroll
    for (int i = 0; i < VPT; i++) {
        int4 ti = t4[tid + i * TPB];
        float px = v[i].x * rinv;
        float py = v[i].y * rinv;
        float pz = v[i].z * rinv;
        float pw = v[i].w * rinv;
        a += (__expf(px) + __expf(py)) + (__expf(pz) + __expf(pw));
        if (ti.x == 1) b += px;
        if (ti.y == 1) b += py;
        if (ti.z == 1) b += pz;
        if (ti.w == 1) b += pw;
    }
    const float A = block_reduce_sum(a, sh, tid);
    const float M = block_reduce_sum(b, sh, tid);

    if (tid == 0) g_losses[row] = __logf(A) - M;
}

// Deterministic fixed-order mean over the 16384 per-row losses.
__global__ __launch_bounds__(1024)
void ce_mean_kernel(float* __restrict__ out) {
    __shared__ float sh[32];
    const int tid = threadIdx.x;
    float s = 0.0f;
#pragma unroll
    for (int i = 0; i < B_ROWS / 1024; i++) s += g_losses[tid + i * 1024];
    s = warp_reduce_sum(s);
    if ((tid & 31) == 0) sh[tid >> 5] = s;
    __syncthreads();
    if (tid < 32) {
        float r = sh[tid];
        r = warp_reduce_sum(r);
        if (tid == 0) out[0] = r * (1.0f / (float)B_ROWS);
    }
}

extern "C" void kernel_launch(void* const* d_in, const int* in_sizes, int n_in,
                              void* d_out, int out_size) {
    const float* x = (const float*)d_in[0];   // output logits, fp32 [B, C]
    const int*   t = (const int*)d_in[1];     // target multi-hot, int32 [B, C]
    float* out = (float*)d_out;               // scalar fp32

    ce_row_kernel<<<B_ROWS, TPB>>>(x, t);
    ce_mean_kernel<<<1, 1024>>>(out);
}